// round 5
// baseline (speedup 1.0000x reference)
#include <cuda_runtime.h>
#include <cuda_bf16.h>

// Problem shapes (fixed by the dataset)
#define BSZ   2048
#define NIN   128
#define NHID  512
#define NOUT  128
#define NB    8          // G+K basis functions
#define NF    9          // features per scalar: silu + 8 basis
#define K1    (NIN * NF)   // 1152
#define K2    (NHID * NF)  // 4608
#define KSPLIT 4
#define KCHUNK2 (K2 / KSPLIT) // 1152

// ----- device scratch (static, no runtime allocation) -----
__device__ float g_W1[K1 * NHID];            // folded weights layer1  [K1][NHID]
__device__ float g_W2[K2 * NOUT];            // folded weights layer2  [K2][NOUT]
__device__ float g_F1[BSZ * K1];             // expanded features layer1
__device__ float g_H [BSZ * NHID];           // hidden activations
__device__ float g_F2[BSZ * K2];             // expanded features layer2
__device__ float g_P2[KSPLIT * BSZ * NOUT];  // split-K partials layer2

// ---------------------------------------------------------------------------
// Fold: W[(i*9+0), o] = scale_base[i,o];  W[(i*9+1+k), o] = scale_sp[i,o]*coef[i,o,k]
// ---------------------------------------------------------------------------
__global__ void fold_kernel(const float* __restrict__ coef,
                            const float* __restrict__ sbase,
                            const float* __restrict__ ssp,
                            float* __restrict__ W,
                            int nIn, int nOut)
{
    int idx = blockIdx.x * blockDim.x + threadIdx.x;
    if (idx >= nIn * nOut) return;
    int i = idx / nOut;
    int o = idx - i * nOut;
    float sb = sbase[idx];
    float sp = ssp[idx];
    const float* c = coef + (size_t)idx * NB;   // coef[i, o, :]
    float* w = W + (size_t)(i * NF) * nOut + o;
    w[0] = sb;
    #pragma unroll
    for (int f = 0; f < NB; f++)
        w[(size_t)(1 + f) * nOut] = sp * c[f];
}

// ---------------------------------------------------------------------------
// Expand: per (b,i) emit [silu(x), B_0..B_7] with Cox–de Boor on grid row i.
// ---------------------------------------------------------------------------
__global__ void expand_kernel(const float* __restrict__ x,
                              const float* __restrict__ grid,
                              float* __restrict__ F,
                              int nIn, int total)
{
    int idx = blockIdx.x * blockDim.x + threadIdx.x;
    if (idx >= total) return;
    int i = idx % nIn;
    float xv = x[idx];

    float t[12];
    const float* g = grid + (size_t)i * 12;
    #pragma unroll
    for (int j = 0; j < 12; j++) t[j] = g[j];

    float Bv[11];
    #pragma unroll
    for (int j = 0; j < 11; j++)
        Bv[j] = (xv >= t[j] && xv < t[j + 1]) ? 1.0f : 0.0f;

    #pragma unroll
    for (int p = 1; p <= 3; p++) {
        #pragma unroll
        for (int j = 0; j < 11 - 1; j++) {   // only first 11-p entries meaningful
            if (j < 11 - p) {
                float left  = (xv - t[j])       / (t[j + p]     - t[j]);
                float right = (t[j + p + 1] - xv) / (t[j + p + 1] - t[j + 1]);
                Bv[j] = left * Bv[j] + right * Bv[j + 1];
            }
        }
    }

    float s = xv / (1.0f + __expf(-xv));     // silu

    float* dst = F + (size_t)idx * NF;       // idx = b*nIn + i ; F row length nIn*9
    dst[0] = s;
    #pragma unroll
    for (int f = 0; f < NB; f++) dst[1 + f] = Bv[f];
}

// ---------------------------------------------------------------------------
// Tiled SGEMM: C[z] (+)= A[brow:brow+64, koff:koff+Kchunk] * B[koff:.., bcol:bcol+64]
// 64x64 tile, BK=16, 256 threads, 4x4 microtile. koff = blockIdx.z * Kchunk.
// Each z writes its own partial slab (C + z*partStride) -> deterministic.
// ---------------------------------------------------------------------------
__global__ void __launch_bounds__(256)
gemm_kernel(const float* __restrict__ A, int lda,
            const float* __restrict__ Bm, int ldb,
            float* __restrict__ C, int N,
            int Kchunk, int partStride)
{
    __shared__ float As[16 * 68];   // [k][m], padded to 68 for bank spread + 16B align
    __shared__ float Bs[16 * 64];   // [k][n]

    const int tid  = threadIdx.x;
    const int tn   = tid & 15;          // 0..15  (col group)
    const int tm   = tid >> 4;          // 0..15  (row group)
    const int brow = blockIdx.y * 64;
    const int bcol = blockIdx.x * 64;
    const int koff = blockIdx.z * Kchunk;

    // A-load mapping: row = tid/4 (0..63), kgroup = tid%4 -> 4 consecutive k
    const int a_r = tid >> 2;
    const int a_k = (tid & 3) * 4;
    // B-load mapping: k = tid/16 (0..15), n = (tid%16)*4
    const int b_k = tid >> 4;
    const int b_n = (tid & 15) * 4;

    const float* Arow = A + (size_t)(brow + a_r) * lda + koff + a_k;
    const float* Brow = Bm + (size_t)(koff + b_k) * ldb + bcol + b_n;

    float acc[4][4];
    #pragma unroll
    for (int i = 0; i < 4; i++)
        #pragma unroll
        for (int j = 0; j < 4; j++) acc[i][j] = 0.0f;

    for (int kk = 0; kk < Kchunk; kk += 16) {
        float4 a4 = *reinterpret_cast<const float4*>(Arow + kk);
        float4 b4 = *reinterpret_cast<const float4*>(Brow + (size_t)kk * ldb);

        // transpose-store A into As[k][m]
        As[(a_k + 0) * 68 + a_r] = a4.x;
        As[(a_k + 1) * 68 + a_r] = a4.y;
        As[(a_k + 2) * 68 + a_r] = a4.z;
        As[(a_k + 3) * 68 + a_r] = a4.w;
        *reinterpret_cast<float4*>(&Bs[b_k * 64 + b_n]) = b4;
        __syncthreads();

        #pragma unroll
        for (int k = 0; k < 16; k++) {
            float4 av = *reinterpret_cast<const float4*>(&As[k * 68 + tm * 4]);
            float4 bv = *reinterpret_cast<const float4*>(&Bs[k * 64 + tn * 4]);
            acc[0][0] += av.x * bv.x; acc[0][1] += av.x * bv.y;
            acc[0][2] += av.x * bv.z; acc[0][3] += av.x * bv.w;
            acc[1][0] += av.y * bv.x; acc[1][1] += av.y * bv.y;
            acc[1][2] += av.y * bv.z; acc[1][3] += av.y * bv.w;
            acc[2][0] += av.z * bv.x; acc[2][1] += av.z * bv.y;
            acc[2][2] += av.z * bv.z; acc[2][3] += av.z * bv.w;
            acc[3][0] += av.w * bv.x; acc[3][1] += av.w * bv.y;
            acc[3][2] += av.w * bv.z; acc[3][3] += av.w * bv.w;
        }
        __syncthreads();
    }

    float* Cz = C + (size_t)blockIdx.z * partStride;
    #pragma unroll
    for (int i = 0; i < 4; i++) {
        float4 v = make_float4(acc[i][0], acc[i][1], acc[i][2], acc[i][3]);
        *reinterpret_cast<float4*>(
            &Cz[(size_t)(brow + tm * 4 + i) * N + bcol + tn * 4]) = v;
    }
}

// ---------------------------------------------------------------------------
// Reduce split-K partials (deterministic order)
// ---------------------------------------------------------------------------
__global__ void reduce_kernel(const float* __restrict__ P, float* __restrict__ out, int n)
{
    int i = blockIdx.x * blockDim.x + threadIdx.x;
    if (i >= n) return;
    out[i] = (P[i] + P[n + i]) + (P[2 * n + i] + P[3 * n + i]);
}

// ---------------------------------------------------------------------------
extern "C" void kernel_launch(void* const* d_in, const int* in_sizes, int n_in,
                              void* d_out, int out_size)
{
    const float* state = (const float*)d_in[0];
    const float* grid1 = (const float*)d_in[1];
    const float* coef1 = (const float*)d_in[2];
    const float* sb1   = (const float*)d_in[3];
    const float* sp1   = (const float*)d_in[4];
    const float* grid2 = (const float*)d_in[5];
    const float* coef2 = (const float*)d_in[6];
    const float* sb2   = (const float*)d_in[7];
    const float* sp2   = (const float*)d_in[8];
    float* out = (float*)d_out;

    float *W1, *W2, *F1, *H, *F2, *P2;
    cudaGetSymbolAddress((void**)&W1, g_W1);
    cudaGetSymbolAddress((void**)&W2, g_W2);
    cudaGetSymbolAddress((void**)&F1, g_F1);
    cudaGetSymbolAddress((void**)&H,  g_H);
    cudaGetSymbolAddress((void**)&F2, g_F2);
    cudaGetSymbolAddress((void**)&P2, g_P2);

    // fold weights (independent)
    fold_kernel<<<(NIN * NHID + 255) / 256, 256>>>(coef1, sb1, sp1, W1, NIN, NHID);
    fold_kernel<<<(NHID * NOUT + 255) / 256, 256>>>(coef2, sb2, sp2, W2, NHID, NOUT);

    // layer 1
    expand_kernel<<<(BSZ * NIN + 255) / 256, 256>>>(state, grid1, F1, NIN, BSZ * NIN);
    gemm_kernel<<<dim3(NHID / 64, BSZ / 64, 1), 256>>>(F1, K1, W1, NHID, H, NHID, K1, 0);

    // layer 2 (split-K over 4 chunks for occupancy at N=128)
    expand_kernel<<<(BSZ * NHID + 255) / 256, 256>>>(H, grid2, F2, NHID, BSZ * NHID);
    gemm_kernel<<<dim3(NOUT / 64, BSZ / 64, KSPLIT), 256>>>(F2, K2, W2, NOUT, P2, NOUT,
                                                            KCHUNK2, BSZ * NOUT);
    reduce_kernel<<<(BSZ * NOUT + 255) / 256, 256>>>(P2, out, BSZ * NOUT);
}

// round 9
// speedup vs baseline: 1.1323x; 1.1323x over previous
#include <cuda_runtime.h>
#include <cuda_bf16.h>
#include <cstdint>

// ---------------- problem shapes (fixed) ----------------
#define BSZ   2048
#define NIN   128
#define NHID  512
#define NOUT  128
#define NB    8
#define NF    9
#define K1    (NIN * NF)    // 1152
#define K2    (NHID * NF)   // 4608
#define K1E   (3 * K1)      // 3456  (bf16x3 augmented K)
#define K2E   (3 * K2)      // 13824
#define Z1    6             // split-K slabs layer1 -> KC1 = 576 (9 chunks)
#define Z2    24            // split-K slabs layer2 -> KC2 = 576 (9 chunks)
#define KC1   (K1E / Z1)
#define KC2   (K2E / Z2)
#define BKC   64            // K elements per smem chunk

// ---------------- static device scratch ----------------
__device__ __nv_bfloat16 g_Wt1[(size_t)NHID * K1E];   // B' layer1 [N][3K] K-major
__device__ __nv_bfloat16 g_Wt2[(size_t)NOUT * K2E];   // B' layer2
__device__ __nv_bfloat16 g_F1 [(size_t)BSZ  * K1E];   // A' layer1 [M][3K]
__device__ __nv_bfloat16 g_F2 [(size_t)BSZ  * K2E];   // A' layer2
__device__ float         g_P1 [(size_t)Z1 * BSZ * NHID];
__device__ float         g_P2 [(size_t)Z2 * BSZ * NOUT];

// ---------------- helpers ----------------
__device__ __forceinline__ uint32_t smem_u32(const void* p) {
    uint32_t a;
    asm("{ .reg .u64 t; cvta.to.shared.u64 t, %1; cvt.u32.u64 %0, t; }" : "=r"(a) : "l"(p));
    return a;
}
__device__ __forceinline__ uint32_t swz(uint32_t off) {   // SW128 swizzle
    return off ^ ((off >> 3) & 0x70);
}
__device__ __forceinline__ void cp_async16(uint32_t saddr, const void* gaddr) {
    asm volatile("cp.async.cg.shared.global [%0], [%1], 16;"
                 :: "r"(saddr), "l"(gaddr) : "memory");
}
__device__ __forceinline__ void cp_commit() {
    asm volatile("cp.async.commit_group;" ::: "memory");
}
template <int N>
__device__ __forceinline__ void cp_wait() {
    asm volatile("cp.async.wait_group %0;" :: "n"(N) : "memory");
}
__device__ __forceinline__ void ldsm_x4(uint32_t& r0, uint32_t& r1, uint32_t& r2,
                                        uint32_t& r3, uint32_t addr) {
    asm volatile("ldmatrix.sync.aligned.m8n8.x4.shared.b16 {%0,%1,%2,%3}, [%4];"
                 : "=r"(r0), "=r"(r1), "=r"(r2), "=r"(r3) : "r"(addr));
}
__device__ __forceinline__ void mma16816(float* d, const uint32_t* a, const uint32_t* b) {
    asm volatile(
        "mma.sync.aligned.m16n8k16.row.col.f32.bf16.bf16.f32 "
        "{%0,%1,%2,%3}, {%4,%5,%6,%7}, {%8,%9}, {%0,%1,%2,%3};"
        : "+f"(d[0]), "+f"(d[1]), "+f"(d[2]), "+f"(d[3])
        : "r"(a[0]), "r"(a[1]), "r"(a[2]), "r"(a[3]), "r"(b[0]), "r"(b[1]));
}

// ---------------------------------------------------------------------------
// Fold weights into B' = [w_hi | w_hi | w_lo] rows [N][3K], K-major.
// ---------------------------------------------------------------------------
__global__ void fold_kernel(const float* __restrict__ coef,
                            const float* __restrict__ sbase,
                            const float* __restrict__ ssp,
                            __nv_bfloat16* __restrict__ Wt,
                            int nIn, int nOut, int Ktot)
{
    int idx = blockIdx.x * blockDim.x + threadIdx.x;
    if (idx >= nIn * nOut) return;
    int o = idx / nIn;
    int i = idx - o * nIn;
    int io = i * nOut + o;
    float sb = sbase[io];
    float sp = ssp[io];
    const float* c = coef + (size_t)io * NB;
    float w[NF];
    w[0] = sb;
    #pragma unroll
    for (int f = 0; f < NB; f++) w[1 + f] = sp * c[f];

    __nv_bfloat16* row = Wt + (size_t)o * (3 * Ktot);
    int c0 = i * NF;
    #pragma unroll
    for (int f = 0; f < NF; f++) {
        float v = w[f];
        __nv_bfloat16 hi = __float2bfloat16(v);
        __nv_bfloat16 lo = __float2bfloat16(v - __bfloat162float(hi));
        row[c0 + f]            = hi;
        row[Ktot + c0 + f]     = hi;
        row[2 * Ktot + c0 + f] = lo;
    }
}

// ---------------------------------------------------------------------------
// Expand (optionally summing split-K slabs as input) into A' = [hi | lo | hi].
// ---------------------------------------------------------------------------
__global__ void expand_kernel(const float* __restrict__ x, int zsum, int zstride,
                              const float* __restrict__ grid,
                              __nv_bfloat16* __restrict__ F,
                              int nIn, int Ktot, int total)
{
    int idx = blockIdx.x * blockDim.x + threadIdx.x;
    if (idx >= total) return;
    int b = idx / nIn;
    int i = idx - b * nIn;

    float xv = x[idx];
    for (int z = 1; z < zsum; z++) xv += x[(size_t)z * zstride + idx];

    float t[12];
    const float* g = grid + (size_t)i * 12;
    #pragma unroll
    for (int j = 0; j < 12; j++) t[j] = g[j];

    float Bv[11];
    #pragma unroll
    for (int j = 0; j < 11; j++)
        Bv[j] = (xv >= t[j] && xv < t[j + 1]) ? 1.0f : 0.0f;
    #pragma unroll
    for (int p = 1; p <= 3; p++) {
        #pragma unroll
        for (int j = 0; j < 10; j++) {
            if (j < 11 - p) {
                float left  = (xv - t[j]) / (t[j + p] - t[j]);
                float right = (t[j + p + 1] - xv) / (t[j + p + 1] - t[j + 1]);
                Bv[j] = left * Bv[j] + right * Bv[j + 1];
            }
        }
    }

    float f9[NF];
    f9[0] = xv / (1.0f + __expf(-xv));
    #pragma unroll
    for (int f = 0; f < NB; f++) f9[1 + f] = Bv[f];

    __nv_bfloat16* row = F + (size_t)b * (3 * Ktot);
    int c0 = i * NF;
    #pragma unroll
    for (int f = 0; f < NF; f++) {
        float v = f9[f];
        __nv_bfloat16 hi = __float2bfloat16(v);
        __nv_bfloat16 lo = __float2bfloat16(v - __bfloat162float(hi));
        row[c0 + f]            = hi;
        row[Ktot + c0 + f]     = lo;
        row[2 * Ktot + c0 + f] = hi;
    }
}

// ---------------------------------------------------------------------------
// bf16 GEMM via ldmatrix + mma.sync m16n8k16 (compute_103-safe tensor path).
// 128x128 tile, BK=64 double-buffered via cp.async, split-K over blockIdx.z.
//   A [Mtot][lda] bf16 K-major, B [Ntot][ldb] bf16 K-major, P fp32 slabs.
// Dynamic smem: 1024 align pad + 4 * 16KB = 66560 B.
// ---------------------------------------------------------------------------
__global__ void __launch_bounds__(256)
kan_mma_gemm(const __nv_bfloat16* __restrict__ A, int lda,
             const __nv_bfloat16* __restrict__ Bm, int ldb,
             float* __restrict__ P, int Ntot, int KC, int partStride)
{
    extern __shared__ char dsm[];
    uint32_t tile = (smem_u32(dsm) + 1023u) & ~1023u;
    const uint32_t bufA[2] = { tile,           tile + 32768u };
    const uint32_t bufB[2] = { tile + 16384u,  tile + 49152u };

    const int tid  = threadIdx.x;
    const int wid  = tid >> 5;
    const int lane = tid & 31;
    const int wm   = wid & 1;        // 2 warps along M (64 rows each)
    const int wn   = wid >> 1;       // 4 warps along N (32 cols each)

    const int mrow0 = blockIdx.y * 128;
    const int ncol0 = blockIdx.x * 128;
    const int kbase = blockIdx.z * KC;
    const int nc    = KC >> 6;

    // cooperative async tile load: 128 rows x 64 bf16 (128B rows, SW128)
    const int ld_row = tid >> 3;         // 0..31 (x4 iterations -> 128 rows)
    const int ld_ch  = (tid & 7) * 16;   // byte offset within 128B row
    auto issue_tile = [&](const __nv_bfloat16* g, int ld, int r0, int k0, uint32_t sb) {
        const char* gb = reinterpret_cast<const char*>(g) + (size_t)k0 * 2 + ld_ch;
        #pragma unroll
        for (int j = 0; j < 4; j++) {
            int row = ld_row + j * 32;
            cp_async16(sb + swz((uint32_t)(row * 128) + ld_ch),
                       gb + (size_t)(r0 + row) * ld * 2);
        }
    };

    float acc[4][4][4];
    #pragma unroll
    for (int mt = 0; mt < 4; mt++)
        #pragma unroll
        for (int nt = 0; nt < 4; nt++)
            #pragma unroll
            for (int e = 0; e < 4; e++) acc[mt][nt][e] = 0.0f;

    // per-lane ldmatrix address offsets (within a chunk buffer)
    // A: row = wm*64 + mt*16 + (lane&15); kbyte = ks*32 + (lane>>4)*16
    const uint32_t a_row = (uint32_t)(wm * 64 + (lane & 15));
    const uint32_t a_kb  = (uint32_t)((lane >> 4) * 16);
    // B: row(n) = wn*32 + nt2*16 + ((lane&16)>>1) + (lane&7); kbyte = ks*32 + (lane&8)*2
    const uint32_t b_row = (uint32_t)(wn * 32 + ((lane & 16) >> 1) + (lane & 7));
    const uint32_t b_kb  = (uint32_t)((lane & 8) * 2);

    // prologue
    issue_tile(A, lda, mrow0, kbase, bufA[0]);
    issue_tile(Bm, ldb, ncol0, kbase, bufB[0]);
    cp_commit();

    for (int c = 0; c < nc; c++) {
        const int b = c & 1;
        if (c + 1 < nc) {
            issue_tile(A, lda, mrow0, kbase + (c + 1) * BKC, bufA[b ^ 1]);
            issue_tile(Bm, ldb, ncol0, kbase + (c + 1) * BKC, bufB[b ^ 1]);
            cp_commit();
            cp_wait<1>();
        } else {
            cp_wait<0>();
        }
        __syncthreads();

        const uint32_t cA = bufA[b];
        const uint32_t cB = bufB[b];
        #pragma unroll
        for (int ks = 0; ks < 4; ks++) {
            uint32_t af[4][4], bf[2][4];
            #pragma unroll
            for (int mt = 0; mt < 4; mt++)
                ldsm_x4(af[mt][0], af[mt][1], af[mt][2], af[mt][3],
                        cA + swz((a_row + mt * 16) * 128 + ks * 32 + a_kb));
            #pragma unroll
            for (int nt2 = 0; nt2 < 2; nt2++)
                ldsm_x4(bf[nt2][0], bf[nt2][1], bf[nt2][2], bf[nt2][3],
                        cB + swz((b_row + nt2 * 16) * 128 + ks * 32 + b_kb));
            #pragma unroll
            for (int mt = 0; mt < 4; mt++) {
                #pragma unroll
                for (int nt = 0; nt < 4; nt++)
                    mma16816(acc[mt][nt], af[mt], &bf[nt >> 1][(nt & 1) * 2]);
            }
        }
        __syncthreads();   // compute done before buffer b is overwritten
    }

    // epilogue: direct fp32 stores to split-K slab
    float* Pz = P + (size_t)blockIdx.z * partStride;
    const int er = lane >> 2;          // 0..7
    const int ec = (lane & 3) * 2;     // 0,2,4,6
    #pragma unroll
    for (int mt = 0; mt < 4; mt++) {
        int row = mrow0 + wm * 64 + mt * 16 + er;
        #pragma unroll
        for (int nt = 0; nt < 4; nt++) {
            int col = ncol0 + wn * 32 + nt * 8 + ec;
            float2 v0 = make_float2(acc[mt][nt][0], acc[mt][nt][1]);
            float2 v1 = make_float2(acc[mt][nt][2], acc[mt][nt][3]);
            *reinterpret_cast<float2*>(&Pz[(size_t)row * Ntot + col])       = v0;
            *reinterpret_cast<float2*>(&Pz[(size_t)(row + 8) * Ntot + col]) = v1;
        }
    }
}

// ---------------------------------------------------------------------------
// Deterministic split-K slab reduce
// ---------------------------------------------------------------------------
__global__ void reduce_kernel(const float* __restrict__ P, float* __restrict__ out,
                              int n, int z)
{
    int i = blockIdx.x * blockDim.x + threadIdx.x;
    if (i >= n) return;
    float s = 0.0f;
    for (int j = 0; j < z; j++) s += P[(size_t)j * n + i];
    out[i] = s;
}

// ---------------------------------------------------------------------------
extern "C" void kernel_launch(void* const* d_in, const int* in_sizes, int n_in,
                              void* d_out, int out_size)
{
    const float* state = (const float*)d_in[0];
    const float* grid1 = (const float*)d_in[1];
    const float* coef1 = (const float*)d_in[2];
    const float* sb1   = (const float*)d_in[3];
    const float* sp1   = (const float*)d_in[4];
    const float* grid2 = (const float*)d_in[5];
    const float* coef2 = (const float*)d_in[6];
    const float* sb2   = (const float*)d_in[7];
    const float* sp2   = (const float*)d_in[8];
    float* out = (float*)d_out;

    __nv_bfloat16 *Wt1, *Wt2, *F1, *F2;
    float *P1, *P2;
    cudaGetSymbolAddress((void**)&Wt1, g_Wt1);
    cudaGetSymbolAddress((void**)&Wt2, g_Wt2);
    cudaGetSymbolAddress((void**)&F1,  g_F1);
    cudaGetSymbolAddress((void**)&F2,  g_F2);
    cudaGetSymbolAddress((void**)&P1,  g_P1);
    cudaGetSymbolAddress((void**)&P2,  g_P2);

    const int GEMM_SMEM = 66560;   // 1024 pad + 64KB double-buffered tiles
    cudaFuncSetAttribute(kan_mma_gemm, cudaFuncAttributeMaxDynamicSharedMemorySize,
                         GEMM_SMEM);

    // fold weights (independent of data path)
    fold_kernel<<<(NIN * NHID + 255) / 256, 256>>>(coef1, sb1, sp1, Wt1, NIN, NHID, K1);
    fold_kernel<<<(NHID * NOUT + 255) / 256, 256>>>(coef2, sb2, sp2, Wt2, NHID, NOUT, K2);

    // layer 1
    expand_kernel<<<(BSZ * NIN + 255) / 256, 256>>>(state, 1, 0, grid1, F1, NIN, K1,
                                                    BSZ * NIN);
    kan_mma_gemm<<<dim3(NHID / 128, BSZ / 128, Z1), 256, GEMM_SMEM>>>(
        F1, K1E, Wt1, K1E, P1, NHID, KC1, BSZ * NHID);

    // layer 2 (expand fuses the slab reduction of P1)
    expand_kernel<<<(BSZ * NHID + 255) / 256, 256>>>(P1, Z1, BSZ * NHID, grid2, F2,
                                                     NHID, K2, BSZ * NHID);
    kan_mma_gemm<<<dim3(NOUT / 128, BSZ / 128, Z2), 256, GEMM_SMEM>>>(
        F2, K2E, Wt2, K2E, P2, NOUT, KC2, BSZ * NOUT);

    reduce_kernel<<<(BSZ * NOUT + 255) / 256, 256>>>(P2, out, BSZ * NOUT, Z2);
}

// round 11
// speedup vs baseline: 1.8467x; 1.6309x over previous
#include <cuda_runtime.h>
#include <cuda_bf16.h>
#include <cstdint>

// ---------------- problem shapes (fixed) ----------------
#define BSZ   2048
#define NIN   128
#define NHID  512
#define NOUT  128
#define NB    8
#define NF    9
#define K1    (NIN * NF)    // 1152
#define K2    (NHID * NF)   // 4608
#define K1E   (3 * K1)      // 3456  (bf16x3 augmented K)
#define K2E   (3 * K2)      // 13824
#define Z1    6             // split-K slabs layer1 -> KC1 = 576 (9 chunks)
#define Z2    24            // split-K slabs layer2 -> KC2 = 576 (9 chunks)
#define KC1   (K1E / Z1)
#define KC2   (K2E / Z2)
#define BKC   64            // K elements per smem chunk

// K ordering (f-major, GEMM-invariant permutation):
//   k = region*Ktot + f*nIn + i ,  region in {0,1,2}
// A' regions = [hi | lo | hi],  B' regions = [hi | hi | lo]
// => coalesced bf16x2 stores in expand/fold.

// ---------------- static device scratch ----------------
__device__ __nv_bfloat16 g_Wt1[(size_t)NHID * K1E];   // B' layer1 [N][3K] K-major
__device__ __nv_bfloat16 g_Wt2[(size_t)NOUT * K2E];   // B' layer2
__device__ __nv_bfloat16 g_F1 [(size_t)BSZ  * K1E];   // A' layer1 [M][3K]
__device__ __nv_bfloat16 g_F2 [(size_t)BSZ  * K2E];   // A' layer2
__device__ float         g_P1 [(size_t)Z1 * BSZ * NHID];
__device__ float         g_P2 [(size_t)Z2 * BSZ * NOUT];

// ---------------- helpers ----------------
__device__ __forceinline__ uint32_t smem_u32(const void* p) {
    uint32_t a;
    asm("{ .reg .u64 t; cvta.to.shared.u64 t, %1; cvt.u32.u64 %0, t; }" : "=r"(a) : "l"(p));
    return a;
}
__device__ __forceinline__ uint32_t swz(uint32_t off) {   // SW128 swizzle
    return off ^ ((off >> 3) & 0x70);
}
__device__ __forceinline__ void cp_async16(uint32_t saddr, const void* gaddr) {
    asm volatile("cp.async.cg.shared.global [%0], [%1], 16;"
                 :: "r"(saddr), "l"(gaddr) : "memory");
}
__device__ __forceinline__ void cp_commit() {
    asm volatile("cp.async.commit_group;" ::: "memory");
}
template <int N>
__device__ __forceinline__ void cp_wait() {
    asm volatile("cp.async.wait_group %0;" :: "n"(N) : "memory");
}
__device__ __forceinline__ void ldsm_x4(uint32_t& r0, uint32_t& r1, uint32_t& r2,
                                        uint32_t& r3, uint32_t addr) {
    asm volatile("ldmatrix.sync.aligned.m8n8.x4.shared.b16 {%0,%1,%2,%3}, [%4];"
                 : "=r"(r0), "=r"(r1), "=r"(r2), "=r"(r3) : "r"(addr));
}
__device__ __forceinline__ void mma16816(float* d, const uint32_t* a, const uint32_t* b) {
    asm volatile(
        "mma.sync.aligned.m16n8k16.row.col.f32.bf16.bf16.f32 "
        "{%0,%1,%2,%3}, {%4,%5,%6,%7}, {%8,%9}, {%0,%1,%2,%3};"
        : "+f"(d[0]), "+f"(d[1]), "+f"(d[2]), "+f"(d[3])
        : "r"(a[0]), "r"(a[1]), "r"(a[2]), "r"(a[3]), "r"(b[0]), "r"(b[1]));
}

// ---------------------------------------------------------------------------
// Fold weights -> B' [N][3K] f-major K: k = r*Ktot + f*nIn + i.
// regions [hi | hi | lo]. Coalesced 2B stores (i fastest across threads).
// ---------------------------------------------------------------------------
__global__ void fold_kernel(const float* __restrict__ coef,
                            const float* __restrict__ sbase,
                            const float* __restrict__ ssp,
                            __nv_bfloat16* __restrict__ Wt,
                            int nIn, int nOut, int Ktot)
{
    int idx = blockIdx.x * blockDim.x + threadIdx.x;
    if (idx >= nIn * nOut) return;
    int o = idx / nIn;
    int i = idx - o * nIn;
    int io = i * nOut + o;
    float sb = sbase[io];
    float sp = ssp[io];
    const float* c = coef + (size_t)io * NB;
    float w[NF];
    w[0] = sb;
    #pragma unroll
    for (int f = 0; f < NB; f++) w[1 + f] = sp * c[f];

    __nv_bfloat16* row = Wt + (size_t)o * (3 * Ktot);
    #pragma unroll
    for (int f = 0; f < NF; f++) {
        float v = w[f];
        __nv_bfloat16 hi = __float2bfloat16(v);
        __nv_bfloat16 lo = __float2bfloat16(v - __bfloat162float(hi));
        int k = f * nIn + i;
        row[k]            = hi;
        row[Ktot + k]     = hi;
        row[2 * Ktot + k] = lo;
    }
}

// ---------------------------------------------------------------------------
// Expand (optionally summing split-K slabs of x) -> A' [B][3K], f-major K,
// regions [hi | lo | hi]. Each thread handles TWO adjacent i -> bf16x2
// fully-coalesced 4B stores (27 per thread).
// ---------------------------------------------------------------------------
__global__ void expand_kernel(const float* __restrict__ x, int zsum, int zstride,
                              const float* __restrict__ grid,
                              __nv_bfloat16* __restrict__ F,
                              int nIn, int Ktot, int totalPairs)
{
    int p = blockIdx.x * blockDim.x + threadIdx.x;
    if (p >= totalPairs) return;
    const int halfIn = nIn >> 1;
    int b  = p / halfIn;
    int ii = (p - b * halfIn) * 2;

    float xv[2];
    #pragma unroll
    for (int e = 0; e < 2; e++) {
        int gidx = b * nIn + ii + e;
        float v = x[gidx];
        for (int z = 1; z < zsum; z++) v += x[(size_t)z * zstride + gidx];
        xv[e] = v;
    }

    float f9[2][NF];
    #pragma unroll
    for (int e = 0; e < 2; e++) {
        const float* g = grid + (size_t)(ii + e) * 12;
        float t[12];
        #pragma unroll
        for (int j = 0; j < 12; j++) t[j] = g[j];

        float Bv[11];
        #pragma unroll
        for (int j = 0; j < 11; j++)
            Bv[j] = (xv[e] >= t[j] && xv[e] < t[j + 1]) ? 1.0f : 0.0f;
        #pragma unroll
        for (int q = 1; q <= 3; q++) {
            #pragma unroll
            for (int j = 0; j < 10; j++) {
                if (j < 11 - q) {
                    float left  = (xv[e] - t[j]) / (t[j + q] - t[j]);
                    float right = (t[j + q + 1] - xv[e]) / (t[j + q + 1] - t[j + 1]);
                    Bv[j] = left * Bv[j] + right * Bv[j + 1];
                }
            }
        }
        f9[e][0] = xv[e] / (1.0f + __expf(-xv[e]));
        #pragma unroll
        for (int f = 0; f < NB; f++) f9[e][1 + f] = Bv[f];
    }

    __nv_bfloat16* row = F + (size_t)b * (3 * Ktot);
    #pragma unroll
    for (int f = 0; f < NF; f++) {
        __nv_bfloat16 h0 = __float2bfloat16(f9[0][f]);
        __nv_bfloat16 h1 = __float2bfloat16(f9[1][f]);
        __nv_bfloat162 hi2; hi2.x = h0; hi2.y = h1;
        __nv_bfloat162 lo2;
        lo2.x = __float2bfloat16(f9[0][f] - __bfloat162float(h0));
        lo2.y = __float2bfloat16(f9[1][f] - __bfloat162float(h1));
        int k = f * nIn + ii;
        *reinterpret_cast<__nv_bfloat162*>(&row[k])            = hi2;  // region 0: hi
        *reinterpret_cast<__nv_bfloat162*>(&row[Ktot + k])     = lo2;  // region 1: lo
        *reinterpret_cast<__nv_bfloat162*>(&row[2 * Ktot + k]) = hi2;  // region 2: hi
    }
}

// ---------------------------------------------------------------------------
// bf16 GEMM via ldmatrix + mma.sync m16n8k16 (compute_103-safe tensor path).
// 128x128 tile, BK=64 double-buffered via cp.async, split-K over blockIdx.z.
//   A [Mtot][lda] bf16 K-major, B [Ntot][ldb] bf16 K-major, P fp32 slabs.
// Dynamic smem: 1024 align pad + 4 * 16KB = 66560 B.
// ---------------------------------------------------------------------------
__global__ void __launch_bounds__(256)
kan_mma_gemm(const __nv_bfloat16* __restrict__ A, int lda,
             const __nv_bfloat16* __restrict__ Bm, int ldb,
             float* __restrict__ P, int Ntot, int KC, int partStride)
{
    extern __shared__ char dsm[];
    uint32_t tile = (smem_u32(dsm) + 1023u) & ~1023u;
    const uint32_t bufA[2] = { tile,           tile + 32768u };
    const uint32_t bufB[2] = { tile + 16384u,  tile + 49152u };

    const int tid  = threadIdx.x;
    const int wid  = tid >> 5;
    const int lane = tid & 31;
    const int wm   = wid & 1;        // 2 warps along M (64 rows each)
    const int wn   = wid >> 1;       // 4 warps along N (32 cols each)

    const int mrow0 = blockIdx.y * 128;
    const int ncol0 = blockIdx.x * 128;
    const int kbase = blockIdx.z * KC;
    const int nc    = KC >> 6;

    // cooperative async tile load: 128 rows x 64 bf16 (128B rows, SW128)
    const int ld_row = tid >> 3;         // 0..31 (x4 iterations -> 128 rows)
    const int ld_ch  = (tid & 7) * 16;   // byte offset within 128B row
    auto issue_tile = [&](const __nv_bfloat16* g, int ld, int r0, int k0, uint32_t sb) {
        const char* gb = reinterpret_cast<const char*>(g) + (size_t)k0 * 2 + ld_ch;
        #pragma unroll
        for (int j = 0; j < 4; j++) {
            int row = ld_row + j * 32;
            cp_async16(sb + swz((uint32_t)(row * 128) + ld_ch),
                       gb + (size_t)(r0 + row) * ld * 2);
        }
    };

    float acc[4][4][4];
    #pragma unroll
    for (int mt = 0; mt < 4; mt++)
        #pragma unroll
        for (int nt = 0; nt < 4; nt++)
            #pragma unroll
            for (int e = 0; e < 4; e++) acc[mt][nt][e] = 0.0f;

    // per-lane ldmatrix address offsets (within a chunk buffer)
    const uint32_t a_row = (uint32_t)(wm * 64 + (lane & 15));
    const uint32_t a_kb  = (uint32_t)((lane >> 4) * 16);
    const uint32_t b_row = (uint32_t)(wn * 32 + ((lane & 16) >> 1) + (lane & 7));
    const uint32_t b_kb  = (uint32_t)((lane & 8) * 2);

    // prologue
    issue_tile(A, lda, mrow0, kbase, bufA[0]);
    issue_tile(Bm, ldb, ncol0, kbase, bufB[0]);
    cp_commit();

    for (int c = 0; c < nc; c++) {
        const int b = c & 1;
        if (c + 1 < nc) {
            issue_tile(A, lda, mrow0, kbase + (c + 1) * BKC, bufA[b ^ 1]);
            issue_tile(Bm, ldb, ncol0, kbase + (c + 1) * BKC, bufB[b ^ 1]);
            cp_commit();
            cp_wait<1>();
        } else {
            cp_wait<0>();
        }
        __syncthreads();

        const uint32_t cA = bufA[b];
        const uint32_t cB = bufB[b];
        #pragma unroll
        for (int ks = 0; ks < 4; ks++) {
            uint32_t af[4][4], bf[2][4];
            #pragma unroll
            for (int mt = 0; mt < 4; mt++)
                ldsm_x4(af[mt][0], af[mt][1], af[mt][2], af[mt][3],
                        cA + swz((a_row + mt * 16) * 128 + ks * 32 + a_kb));
            #pragma unroll
            for (int nt2 = 0; nt2 < 2; nt2++)
                ldsm_x4(bf[nt2][0], bf[nt2][1], bf[nt2][2], bf[nt2][3],
                        cB + swz((b_row + nt2 * 16) * 128 + ks * 32 + b_kb));
            #pragma unroll
            for (int mt = 0; mt < 4; mt++) {
                #pragma unroll
                for (int nt = 0; nt < 4; nt++)
                    mma16816(acc[mt][nt], af[mt], &bf[nt >> 1][(nt & 1) * 2]);
            }
        }
        __syncthreads();   // compute done before buffer b is overwritten
    }

    // epilogue: direct fp32 stores to split-K slab
    float* Pz = P + (size_t)blockIdx.z * partStride;
    const int er = lane >> 2;          // 0..7
    const int ec = (lane & 3) * 2;     // 0,2,4,6
    #pragma unroll
    for (int mt = 0; mt < 4; mt++) {
        int row = mrow0 + wm * 64 + mt * 16 + er;
        #pragma unroll
        for (int nt = 0; nt < 4; nt++) {
            int col = ncol0 + wn * 32 + nt * 8 + ec;
            float2 v0 = make_float2(acc[mt][nt][0], acc[mt][nt][1]);
            float2 v1 = make_float2(acc[mt][nt][2], acc[mt][nt][3]);
            *reinterpret_cast<float2*>(&Pz[(size_t)row * Ntot + col])       = v0;
            *reinterpret_cast<float2*>(&Pz[(size_t)(row + 8) * Ntot + col]) = v1;
        }
    }
}

// ---------------------------------------------------------------------------
// Deterministic split-K slab reduce (float4-vectorized; n % 4 == 0 here)
// ---------------------------------------------------------------------------
__global__ void reduce_kernel(const float* __restrict__ P, float* __restrict__ out,
                              int n, int z)
{
    int i4 = blockIdx.x * blockDim.x + threadIdx.x;
    int nq = n >> 2;
    if (i4 >= nq) return;
    float4 s = make_float4(0.f, 0.f, 0.f, 0.f);
    for (int j = 0; j < z; j++) {
        float4 v = *reinterpret_cast<const float4*>(&P[(size_t)j * n + i4 * 4]);
        s.x += v.x; s.y += v.y; s.z += v.z; s.w += v.w;
    }
    *reinterpret_cast<float4*>(&out[i4 * 4]) = s;
}

// ---------------------------------------------------------------------------
extern "C" void kernel_launch(void* const* d_in, const int* in_sizes, int n_in,
                              void* d_out, int out_size)
{
    const float* state = (const float*)d_in[0];
    const float* grid1 = (const float*)d_in[1];
    const float* coef1 = (const float*)d_in[2];
    const float* sb1   = (const float*)d_in[3];
    const float* sp1   = (const float*)d_in[4];
    const float* grid2 = (const float*)d_in[5];
    const float* coef2 = (const float*)d_in[6];
    const float* sb2   = (const float*)d_in[7];
    const float* sp2   = (const float*)d_in[8];
    float* out = (float*)d_out;

    __nv_bfloat16 *Wt1, *Wt2, *F1, *F2;
    float *P1, *P2;
    cudaGetSymbolAddress((void**)&Wt1, g_Wt1);
    cudaGetSymbolAddress((void**)&Wt2, g_Wt2);
    cudaGetSymbolAddress((void**)&F1,  g_F1);
    cudaGetSymbolAddress((void**)&F2,  g_F2);
    cudaGetSymbolAddress((void**)&P1,  g_P1);
    cudaGetSymbolAddress((void**)&P2,  g_P2);

    const int GEMM_SMEM = 66560;   // 1024 pad + 64KB double-buffered tiles
    cudaFuncSetAttribute(kan_mma_gemm, cudaFuncAttributeMaxDynamicSharedMemorySize,
                         GEMM_SMEM);

    // fold weights (independent of data path)
    fold_kernel<<<(NIN * NHID + 255) / 256, 256>>>(coef1, sb1, sp1, Wt1, NIN, NHID, K1);
    fold_kernel<<<(NHID * NOUT + 255) / 256, 256>>>(coef2, sb2, sp2, Wt2, NHID, NOUT, K2);

    // layer 1
    {
        int pairs = BSZ * NIN / 2;
        expand_kernel<<<(pairs + 255) / 256, 256>>>(state, 1, 0, grid1, F1, NIN, K1, pairs);
    }
    kan_mma_gemm<<<dim3(NHID / 128, BSZ / 128, Z1), 256, GEMM_SMEM>>>(
        F1, K1E, Wt1, K1E, P1, NHID, KC1, BSZ * NHID);

    // layer 2 (expand fuses the slab reduction of P1)
    {
        int pairs = BSZ * NHID / 2;
        expand_kernel<<<(pairs + 255) / 256, 256>>>(P1, Z1, BSZ * NHID, grid2, F2,
                                                    NHID, K2, pairs);
    }
    kan_mma_gemm<<<dim3(NOUT / 128, BSZ / 128, Z2), 256, GEMM_SMEM>>>(
        F2, K2E, Wt2, K2E, P2, NOUT, KC2, BSZ * NOUT);

    reduce_kernel<<<(BSZ * NOUT / 4 + 255) / 256, 256>>>(P2, out, BSZ * NOUT, Z2);
}